// round 15
// baseline (speedup 1.0000x reference)
#include <cuda_runtime.h>
#include <cuda_fp16.h>

#define NN 50000
#define EE 1250000
#define PAIRJ 312500           // EE/4 thread-groups; each thread does 4 edges (2 pairs)
#define HH 64
#define BB 500
#define BN_EPS 1e-5f

#define NB2 2048
#define XLO (-8.0f)
#define INVH2 128.0f           // NB2/16
#define H2 0.0078125f          // 16/NB2
#define TROWS 2112             // 33*64 >= NB2+1

// ---------------- device scratch ----------------
__device__ float   g_T[TROWS * HH];      // fp32 table at bin edges (pre-affine, for stats)
__device__ uint4   g_Tp[NB2 * 16];       // paired fp16 table: rows (b, b+1) per lane, 512KB
__device__ __half2 g_emh[100 * 32];      // fp16 edge_emb
__device__ __half2 g_hh[NN * 32];        // fp16 node features (gather side), 6.4MB
__device__ int2    g_rec[EE];            // src|dst<<16, ty|bin<<7|wq<<18
__device__ float   g_hist[3 * NB2];      // n, sum(w), sum(w^2)  (quantized w)
__device__ float   g_agg[NN * HH];       // fp32 accumulator
__device__ float   g_hg[BB * HH];
__device__ float   g_y1[NN * 64];
__device__ float   g_y2[NN * 32];
__device__ float   g_red[22592];
__device__ float   g_coef[1024];

#define OFF_X   0
#define OFF_D2  64
#define OFF_C1  4160
#define OFF_C2  8256
#define OFF_C3  12352
#define OFF_O1  16448
#define OFF_O2  20544

__device__ __forceinline__ float sp(float x) {
    float t, l;
    asm("ex2.approx.ftz.f32 %0, %1;" : "=f"(t) : "f"(x * 1.44269504f));
    asm("lg2.approx.f32 %0, %1;" : "=f"(l) : "f"(1.0f + t));
    float r = l * 0.69314718f;
    return x > 20.0f ? x : r;
}

// ---------------- setup kernels ----------------

__global__ void kzero() {
    int i = blockIdx.x * 256 + threadIdx.x;
    if (i < 22592) g_red[i] = 0.0f;
    if (i < BB * HH) g_hg[i] = 0.0f;
    if (i < 3 * NB2) g_hist[i] = 0.0f;
}

// stride-loop over edges: pack records, smem histogram (n, w, w^2), x stats
__global__ void kprep(const int* __restrict__ ei, const int* __restrict__ et,
                      const float* __restrict__ x) {
    __shared__ float hn[NB2], hw[NB2], hw2[NB2];
    __shared__ float sxs[2];
    int t = threadIdx.x;
    for (int i = t; i < NB2; i += 256) { hn[i] = 0; hw[i] = 0; hw2[i] = 0; }
    if (t < 2) sxs[t] = 0.f;
    __syncthreads();

    float sx = 0.f, sxx = 0.f;
    for (int e = blockIdx.x * 256 + t; e < EE; e += gridDim.x * 256) {
        float xv = x[e];
        sx += xv; sxx += xv * xv;
        float u = (xv - XLO) * INVH2;
        u = fminf(fmaxf(u, 0.0f), (float)NB2);
        int b = (int)u; if (b > NB2 - 1) b = NB2 - 1;
        int wq = (int)((u - (float)b) * 16383.0f + 0.5f);
        float w = (float)wq * (1.0f / 16383.0f);
        atomicAdd(&hn[b], 1.0f);
        atomicAdd(&hw[b], w);
        atomicAdd(&hw2[b], w * w);
        g_rec[e] = make_int2(ei[e] | (ei[EE + e] << 16),
                             et[e] | (b << 7) | (wq << 18));
    }
    atomicAdd(&sxs[0], sx);
    atomicAdd(&sxs[1], sxx);
    __syncthreads();
    for (int i = t * 4; i < NB2; i += 1024) {
        float4 a = *(const float4*)&hn[i];
        float4 b = *(const float4*)&hw[i];
        float4 c = *(const float4*)&hw2[i];
        asm volatile("red.global.add.v4.f32 [%0], {%1, %2, %3, %4};"
                     :: "l"(&g_hist[i]), "f"(a.x), "f"(a.y), "f"(a.z), "f"(a.w) : "memory");
        asm volatile("red.global.add.v4.f32 [%0], {%1, %2, %3, %4};"
                     :: "l"(&g_hist[NB2 + i]), "f"(b.x), "f"(b.y), "f"(b.z), "f"(b.w) : "memory");
        asm volatile("red.global.add.v4.f32 [%0], {%1, %2, %3, %4};"
                     :: "l"(&g_hist[2 * NB2 + i]), "f"(c.x), "f"(c.y), "f"(c.z), "f"(c.w) : "memory");
    }
    if (t == 0) {
        int r = blockIdx.x & 31;
        atomicAdd(&g_red[OFF_X + 2 * r], sxs[0]);
        atomicAdd(&g_red[OFF_X + 2 * r + 1], sxs[1]);
    }
}

__global__ void kfin_d1(const float* __restrict__ w_d1, const float* __restrict__ g_d1,
                        const float* __restrict__ be_d1) {
    __shared__ float S[2];
    if (threadIdx.x == 0) {
        float s = 0.f, q = 0.f;
        for (int r = 0; r < 32; r++) { s += g_red[2 * r]; q += g_red[2 * r + 1]; }
        S[0] = s; S[1] = q;
    }
    __syncthreads();
    float mx = S[0] / (float)EE;
    float vx = S[1] / (float)EE - mx * mx;
    int h = threadIdx.x;
    float w = w_d1[h];
    float a = w * rsqrtf(vx * w * w + BN_EPS) * g_d1[h];
    g_coef[h] = a;
    g_coef[64 + h] = -mx * a + be_d1[h];
}

// table build at bin-edge nodes: tiled GEMM, block = 64 rows x 64 k
__global__ void ktable(const float* __restrict__ w_d2) {
    __shared__ float w2s[64 * 68];
    __shared__ float spv[64 * 64];
    int t = threadIdx.x;
    int j0 = blockIdx.x * 64;

    for (int i = t * 4; i < 4096; i += 1024) {
        float4 v = __ldg((const float4*)&w_d2[i]);
        int k = i >> 6, f = i & 63;
        *(float4*)&w2s[k * 68 + f] = v;
    }
    {
        int f = t & 63;
        float a = g_coef[f], c = g_coef[64 + f];
        for (int j = t >> 6; j < 64; j += 4) {
            float xj = XLO + (float)(j0 + j) * H2;
            spv[j * 64 + f] = sp(a * xj + c);
        }
    }
    __syncthreads();

    int k = t & 63;
    int jg = (t >> 6) * 16;
    float acc[16];
#pragma unroll
    for (int i = 0; i < 16; i++) acc[i] = 0.f;
    for (int f4 = 0; f4 < 64; f4 += 4) {
        float4 w4 = *(const float4*)&w2s[k * 68 + f4];
#pragma unroll
        for (int i = 0; i < 16; i++) {
            float4 d = *(const float4*)&spv[(jg + i) * 64 + f4];
            acc[i] += d.x * w4.x + d.y * w4.y + d.z * w4.z + d.w * w4.w;
        }
    }
#pragma unroll
    for (int i = 0; i < 16; i++)
        g_T[(j0 + jg + i) * 64 + k] = acc[i];
}

// BN2 stats from histogram moments; 256 blocks x 64 threads, 8 bins each
__global__ void kd2stat() {
    int k = threadIdx.x;
    int b0 = blockIdx.x * 8;
    float s = 0.f, q = 0.f;
    float tp = g_T[b0 * 64 + k];
    for (int j = 0; j < 8; j++) {
        int b = b0 + j;
        float tn = g_T[(b + 1) * 64 + k];
        float n  = g_hist[b];
        float c1 = g_hist[NB2 + b];
        float s2 = g_hist[2 * NB2 + b];
        float c0 = n - c1;
        float s1 = c1 - s2;
        float s0 = n - 2.0f * c1 + s2;
        s += c0 * tp + c1 * tn;
        q += s0 * tp * tp + 2.0f * s1 * tp * tn + s2 * tn * tn;
        tp = tn;
    }
    int r = blockIdx.x & 31;
    atomicAdd(&g_red[OFF_D2 + r * 128 + k], s);
    atomicAdd(&g_red[OFF_D2 + r * 128 + 64 + k], q);
}

__global__ void kfinbn(int redoff, int F, float cnt, const float* __restrict__ g,
                       const float* __restrict__ be, int coefoff) {
    int k = threadIdx.x;
    if (k >= F) return;
    float s = 0.f, q = 0.f;
    for (int r = 0; r < 32; r++) {
        s += g_red[redoff + r * 2 * F + k];
        q += g_red[redoff + r * 2 * F + F + k];
    }
    float m = s / cnt;
    float v = q / cnt - m * m;
    float sc = g[k] * rsqrtf(v + BN_EPS);
    g_coef[coefoff + k] = sc;
    g_coef[coefoff + 64 + k] = be[k] - m * sc;
}

// fold BN2 affine into paired fp16 table: g_Tp[b*16+l] = {T(b)[4l..4l+3], T(b+1)[4l..4l+3]}
__global__ void ktaffine() {
    int i = blockIdx.x * 256 + threadIdx.x;
    if (i >= NB2 * 16) return;
    int b = i >> 4;
    int f = (i & 15) * 4;
    float sc0 = g_coef[128 + f], sc1 = g_coef[128 + f + 1];
    float sc2 = g_coef[128 + f + 2], sc3 = g_coef[128 + f + 3];
    float sh0 = g_coef[192 + f], sh1 = g_coef[192 + f + 1];
    float sh2 = g_coef[192 + f + 2], sh3 = g_coef[192 + f + 3];
    const float* ra = &g_T[b * 64 + f];
    const float* rb = &g_T[(b + 1) * 64 + f];
    uint4 out;
    *(__half2*)&out.x = __floats2half2_rn(ra[0] * sc0 + sh0, ra[1] * sc1 + sh1);
    *(__half2*)&out.y = __floats2half2_rn(ra[2] * sc2 + sh2, ra[3] * sc3 + sh3);
    *(__half2*)&out.z = __floats2half2_rn(rb[0] * sc0 + sh0, rb[1] * sc1 + sh1);
    *(__half2*)&out.w = __floats2half2_rn(rb[2] * sc2 + sh2, rb[3] * sc3 + sh3);
    g_Tp[i] = out;
}

__global__ void kemh(const float* __restrict__ edge_emb) {
    int i = blockIdx.x * 256 + threadIdx.x;
    if (i >= 100 * 32) return;
    g_emh[i] = __floats2half2_rn(edge_emb[2 * i], edge_emb[2 * i + 1]);
}

__global__ void kinith(const int* __restrict__ node_type, const float* __restrict__ node_emb) {
    int i = blockIdx.x * 256 + threadIdx.x;   // N*32: two features per thread
    int n = i >> 5, k2 = (i & 31) * 2;
    float v0 = node_emb[node_type[n] * 64 + k2];
    float v1 = node_emb[node_type[n] * 64 + k2 + 1];
    g_hh[i] = __floats2half2_rn(v0, v1);
    g_agg[n * 64 + k2] = v0;
    g_agg[n * 64 + k2 + 1] = v1;
}

// ---------------- gconv: 16 thr/edge-slice, 4 edges/thread, fp16 h gather ----------------
__global__ void kedge() {
    int idx = blockIdx.x * 256 + threadIdx.x;
    int j = idx >> 4;
    if (j >= PAIRJ) return;
    int l = idx & 15;
    int l2 = l * 2;
    int f0 = l * 4;

    int4 ra = __ldg(&((const int4*)g_rec)[j]);
    int4 rb = __ldg(&((const int4*)g_rec)[j + PAIRJ]);

    int sd0 = ra.x, mt0 = ra.y;
    int sd1 = ra.z, mt1 = ra.w;
    int sd2 = rb.x, mt2 = rb.y;
    int sd3 = rb.z, mt3 = rb.w;

    int b0 = (mt0 >> 7) & 2047, b1 = (mt1 >> 7) & 2047;
    int b2 = (mt2 >> 7) & 2047, b3 = (mt3 >> 7) & 2047;
    float w0 = (float)((unsigned)mt0 >> 18) * (1.0f / 16383.0f);
    float w1 = (float)((unsigned)mt1 >> 18) * (1.0f / 16383.0f);
    float w2 = (float)((unsigned)mt2 >> 18) * (1.0f / 16383.0f);
    float w3 = (float)((unsigned)mt3 >> 18) * (1.0f / 16383.0f);

    uint4 t0 = __ldg(&g_Tp[b0 * 16 + l]);
    uint4 t1 = __ldg(&g_Tp[b1 * 16 + l]);
    uint4 t2 = __ldg(&g_Tp[b2 * 16 + l]);
    uint4 t3 = __ldg(&g_Tp[b3 * 16 + l]);

    uint2 e0 = __ldg((const uint2*)&g_emh[(mt0 & 127) * 32 + l2]);
    uint2 e1 = __ldg((const uint2*)&g_emh[(mt1 & 127) * 32 + l2]);
    uint2 e2 = __ldg((const uint2*)&g_emh[(mt2 & 127) * 32 + l2]);
    uint2 e3 = __ldg((const uint2*)&g_emh[(mt3 & 127) * 32 + l2]);

    uint2 h0 = __ldg((const uint2*)&g_hh[((unsigned)sd0 & 0xffffu) * 32 + l2]);
    uint2 h1 = __ldg((const uint2*)&g_hh[((unsigned)sd1 & 0xffffu) * 32 + l2]);
    uint2 h2 = __ldg((const uint2*)&g_hh[((unsigned)sd2 & 0xffffu) * 32 + l2]);
    uint2 h3 = __ldg((const uint2*)&g_hh[((unsigned)sd3 & 0xffffu) * 32 + l2]);

#define EDGE_MSG(tp, ee, hh, ww, sd)                                            \
    {                                                                           \
        float2 a0 = __half22float2(*(const __half2*)&tp.x);                     \
        float2 a1 = __half22float2(*(const __half2*)&tp.y);                     \
        float2 c0 = __half22float2(*(const __half2*)&tp.z);                     \
        float2 c1 = __half22float2(*(const __half2*)&tp.w);                     \
        float2 u0 = __half22float2(*(const __half2*)&ee.x);                     \
        float2 u1 = __half22float2(*(const __half2*)&ee.y);                     \
        float2 hA = __half22float2(*(const __half2*)&hh.x);                     \
        float2 hB = __half22float2(*(const __half2*)&hh.y);                     \
        float m0 = sp(hA.x + fmaf(ww, c0.x - a0.x, a0.x) * u0.x);               \
        float m1 = sp(hA.y + fmaf(ww, c0.y - a0.y, a0.y) * u0.y);               \
        float m2 = sp(hB.x + fmaf(ww, c1.x - a1.x, a1.x) * u1.x);               \
        float m3 = sp(hB.y + fmaf(ww, c1.y - a1.y, a1.y) * u1.y);               \
        float* o = &g_agg[((unsigned)sd >> 16) * 64 + f0];                      \
        asm volatile("red.global.add.v4.f32 [%0], {%1, %2, %3, %4};"            \
                     :: "l"(o), "f"(m0), "f"(m1), "f"(m2), "f"(m3) : "memory"); \
    }

    EDGE_MSG(t0, e0, h0, w0, sd0)
    EDGE_MSG(t1, e1, h1, w1, sd1)
    EDGE_MSG(t2, e2, h2, w2, sd2)
    EDGE_MSG(t3, e3, h3, w3, sd3)
#undef EDGE_MSG
}

// node stats: 782 blocks x 256 thr; each block covers 64 nodes with 4 independent loads/thread
__global__ void knstat(int redoff) {
    int t = threadIdx.x;
    int f0 = (t & 15) * 4;
    int n0 = blockIdx.x * 64 + (t >> 4);
    float4 v0, v1, v2, v3;
    bool k0 = (n0 < NN), k1 = (n0 + 16 < NN), k2 = (n0 + 32 < NN), k3 = (n0 + 48 < NN);
    if (k0) v0 = *(const float4*)&g_agg[n0 * 64 + f0];
    if (k1) v1 = *(const float4*)&g_agg[(n0 + 16) * 64 + f0];
    if (k2) v2 = *(const float4*)&g_agg[(n0 + 32) * 64 + f0];
    if (k3) v3 = *(const float4*)&g_agg[(n0 + 48) * 64 + f0];
    float4 s = {0, 0, 0, 0}, q = {0, 0, 0, 0};
#define ACC(vv, kk)                                                     \
    if (kk) {                                                           \
        s.x += vv.x; s.y += vv.y; s.z += vv.z; s.w += vv.w;             \
        q.x += vv.x * vv.x; q.y += vv.y * vv.y;                         \
        q.z += vv.z * vv.z; q.w += vv.w * vv.w;                         \
    }
    ACC(v0, k0) ACC(v1, k1) ACC(v2, k2) ACC(v3, k3)
#undef ACC
    __shared__ float ssum[64], ssq[64];
    if (t < 64) { ssum[t] = 0.f; ssq[t] = 0.f; }
    __syncthreads();
    atomicAdd(&ssum[f0 + 0], s.x); atomicAdd(&ssum[f0 + 1], s.y);
    atomicAdd(&ssum[f0 + 2], s.z); atomicAdd(&ssum[f0 + 3], s.w);
    atomicAdd(&ssq[f0 + 0], q.x); atomicAdd(&ssq[f0 + 1], q.y);
    atomicAdd(&ssq[f0 + 2], q.z); atomicAdd(&ssq[f0 + 3], q.w);
    __syncthreads();
    if (t < 64) {
        int r = blockIdx.x & 31;
        atomicAdd(&g_red[redoff + r * 128 + t], ssum[t]);
        atomicAdd(&g_red[redoff + r * 128 + 64 + t], ssq[t]);
    }
}

__global__ void kapply(int coefoff, int doact, int dohg, const int* __restrict__ batch) {
    int i = blockIdx.x * 256 + threadIdx.x;
    int n = i >> 4;
    int f0 = (i & 15) * 4;
    float4 v  = *(const float4*)&g_agg[n * 64 + f0];
    float4 sc = *(const float4*)&g_coef[coefoff + f0];
    float4 sh = *(const float4*)&g_coef[coefoff + 64 + f0];
    v.x = v.x * sc.x + sh.x; v.y = v.y * sc.y + sh.y;
    v.z = v.z * sc.z + sh.z; v.w = v.w * sc.w + sh.w;
    if (doact) {
        v.x = sp(v.x); v.y = sp(v.y); v.z = sp(v.z); v.w = sp(v.w);
        uint2 hout;
        *(__half2*)&hout.x = __floats2half2_rn(v.x, v.y);
        *(__half2*)&hout.y = __floats2half2_rn(v.z, v.w);
        *(uint2*)&g_hh[n * 32 + (i & 15) * 2] = hout;   // gather copy for next kedge
    }
    *(float4*)&g_agg[n * 64 + f0] = v;   // fp32 h (self term / output stage)
    if (dohg) {
        int b = batch[n];
        float* o = &g_hg[b * 64 + f0];
        asm volatile("red.global.add.v4.f32 [%0], {%1, %2, %3, %4};"
                     :: "l"(o), "f"(v.x), "f"(v.y), "f"(v.z), "f"(v.w) : "memory");
    }
}

// out MLP stage 1: 16 nodes per block; reads fp32 h from g_agg
__global__ void kstage1(const int* __restrict__ batch, const float* __restrict__ w_o1,
                        const float* __restrict__ b_o1) {
    __shared__ float snf[4][128];
    __shared__ float ssum[64], ssq[64];
    int t = threadIdx.x, q = t >> 6, k = t & 63;
    float asum = 0.f, asq = 0.f;
    float bias = b_o1[k];
#pragma unroll 1
    for (int it = 0; it < 4; it++) {
        int n = blockIdx.x * 16 + it * 4 + q;
        __syncthreads();
        snf[q][k]      = g_agg[n * 64 + k];
        snf[q][64 + k] = g_hg[batch[n] * 64 + k];
        __syncthreads();
        float acc = bias;
#pragma unroll
        for (int j4 = 0; j4 < 32; j4++) {
            float4 w4 = __ldg((const float4*)&w_o1[k * 128 + j4 * 4]);
            float4 v = *(const float4*)&snf[q][j4 * 4];
            acc += v.x * w4.x + v.y * w4.y + v.z * w4.z + v.w * w4.w;
        }
        g_y1[n * 64 + k] = acc;
        asum += acc; asq += acc * acc;
    }
    if (t < 64) { ssum[t] = 0.f; ssq[t] = 0.f; }
    __syncthreads();
    atomicAdd(&ssum[k], asum);
    atomicAdd(&ssq[k], asq);
    __syncthreads();
    if (t < 64) {
        int r = blockIdx.x & 31;
        atomicAdd(&g_red[OFF_O1 + r * 128 + t], ssum[t]);
        atomicAdd(&g_red[OFF_O1 + r * 128 + 64 + t], ssq[t]);
    }
}

// stage 2: 16 nodes per block
__global__ void kstage2(const float* __restrict__ w_o2, const float* __restrict__ b_o2) {
    __shared__ float sv[4][64];
    __shared__ float ssum[32], ssq[32];
    int t = threadIdx.x, q = t >> 5, k = t & 31;
    float asum = 0.f, asq = 0.f;
    float bias = b_o2[k];
#pragma unroll 1
    for (int it = 0; it < 4; it++) {
        int n = blockIdx.x * 16 + it * 4 + q;
        __syncthreads();
        {
            float a = g_y1[n * 64 + k]      * g_coef[640 + k]      + g_coef[704 + k];
            float b = g_y1[n * 64 + 32 + k] * g_coef[640 + 32 + k] + g_coef[704 + 32 + k];
            sv[q][k] = sp(a);
            sv[q][32 + k] = sp(b);
        }
        __syncthreads();
        float acc = bias;
#pragma unroll
        for (int j4 = 0; j4 < 16; j4++) {
            float4 w4 = __ldg((const float4*)&w_o2[k * 64 + j4 * 4]);
            float4 v = *(const float4*)&sv[q][j4 * 4];
            acc += v.x * w4.x + v.y * w4.y + v.z * w4.z + v.w * w4.w;
        }
        g_y2[n * 32 + k] = acc;
        asum += acc; asq += acc * acc;
    }
    if (t < 32) { ssum[t] = 0.f; ssq[t] = 0.f; }
    __syncthreads();
    atomicAdd(&ssum[k], asum);
    atomicAdd(&ssq[k], asq);
    __syncthreads();
    if (t < 32) {
        int r = blockIdx.x & 31;
        atomicAdd(&g_red[OFF_O2 + r * 64 + t], ssum[t]);
        atomicAdd(&g_red[OFF_O2 + r * 64 + 32 + t], ssq[t]);
    }
}

// stage 3: 16 nodes per block (8 iterations of 2)
__global__ void kstage3(const float* __restrict__ w_o3, const float* __restrict__ b_o3,
                        float* __restrict__ out) {
    __shared__ float sv[2][32];
    int t = threadIdx.x;
    int q = t >> 7, c = t & 127;
    float bias = b_o3[c];
#pragma unroll 1
    for (int it = 0; it < 8; it++) {
        int n2 = blockIdx.x * 16 + it * 2;
        __syncthreads();
        if (t < 64) {
            int qq = t >> 5, k = t & 31;
            float a = g_y2[(n2 + qq) * 32 + k] * g_coef[768 + k] + g_coef[832 + k];
            sv[qq][k] = sp(a);
        }
        __syncthreads();
        int n = n2 + q;
        float acc = bias;
#pragma unroll
        for (int j4 = 0; j4 < 8; j4++) {
            float4 w4 = __ldg((const float4*)&w_o3[c * 32 + j4 * 4]);
            float4 v = *(const float4*)&sv[q][j4 * 4];
            acc += v.x * w4.x + v.y * w4.y + v.z * w4.z + v.w * w4.w;
        }
        if (c < 64) out[(long)n * 64 + c] = acc;
        else        out[(long)NN * 64 + (long)n * 64 + (c - 64)] = acc;
    }
}

// ---------------- launch ----------------
extern "C" void kernel_launch(void* const* d_in, const int* in_sizes, int n_in,
                              void* d_out, int out_size) {
    const float* x         = (const float*)d_in[0];
    const int*   node_type = (const int*)d_in[1];
    const int*   edge_type = (const int*)d_in[2];
    const int*   edge_index= (const int*)d_in[3];
    const int*   batch     = (const int*)d_in[4];
    const float* node_emb  = (const float*)d_in[5];
    const float* edge_emb  = (const float*)d_in[6];
    const float* w_d1      = (const float*)d_in[7];
    const float* g_d1      = (const float*)d_in[9];
    const float* be_d1     = (const float*)d_in[10];
    const float* w_d2      = (const float*)d_in[11];
    const float* g_d2      = (const float*)d_in[13];
    const float* be_d2     = (const float*)d_in[14];
    const float* g_c1      = (const float*)d_in[15];
    const float* be_c1     = (const float*)d_in[16];
    const float* g_c2      = (const float*)d_in[17];
    const float* be_c2     = (const float*)d_in[18];
    const float* g_c3      = (const float*)d_in[19];
    const float* be_c3     = (const float*)d_in[20];
    const float* w_o1      = (const float*)d_in[21];
    const float* b_o1      = (const float*)d_in[22];
    const float* g_o1      = (const float*)d_in[23];
    const float* be_o1     = (const float*)d_in[24];
    const float* w_o2      = (const float*)d_in[25];
    const float* b_o2      = (const float*)d_in[26];
    const float* g_o2      = (const float*)d_in[27];
    const float* be_o2     = (const float*)d_in[28];
    const float* w_o3      = (const float*)d_in[29];
    const float* b_o3      = (const float*)d_in[30];

    kzero<<<128, 256>>>();
    kprep<<<296, 256>>>(edge_index, edge_type, x);
    kfin_d1<<<1, 64>>>(w_d1, g_d1, be_d1);
    ktable<<<TROWS / 64, 256>>>(w_d2);
    kd2stat<<<NB2 / 8, 64>>>();
    kfinbn<<<1, 64>>>(OFF_D2, 64, (float)EE, g_d2, be_d2, 128);
    ktaffine<<<(NB2 * 16 + 255) / 256, 256>>>();
    kemh<<<13, 256>>>(edge_emb);
    kinith<<<(NN * 32 + 255) / 256, 256>>>(node_type, node_emb);

    const int   statoff[3] = {OFF_C1, OFF_C2, OFF_C3};
    const int   coefoff[3] = {256, 384, 512};
    const float* gs[3]  = {g_c1, g_c2, g_c3};
    const float* bes[3] = {be_c1, be_c2, be_c3};
    for (int l = 0; l < 3; l++) {
        kedge<<<(PAIRJ * 16 + 255) / 256, 256>>>();
        knstat<<<(NN + 63) / 64, 256>>>(statoff[l]);
        kfinbn<<<1, 64>>>(statoff[l], 64, (float)NN, gs[l], bes[l], coefoff[l]);
        kapply<<<3125, 256>>>(coefoff[l], (l < 2) ? 1 : 0, (l == 2) ? 1 : 0, batch);
    }

    kstage1<<<3125, 256>>>(batch, w_o1, b_o1);
    kfinbn<<<1, 64>>>(OFF_O1, 64, (float)NN, g_o1, be_o1, 640);
    kstage2<<<3125, 128>>>(w_o2, b_o2);
    kfinbn<<<1, 64>>>(OFF_O2, 32, (float)NN, g_o2, be_o2, 768);
    kstage3<<<3125, 256>>>(w_o3, b_o3, (float*)d_out);
}

// round 16
// speedup vs baseline: 1.0008x; 1.0008x over previous
#include <cuda_runtime.h>
#include <cuda_fp16.h>

#define NN 50000
#define EE 1250000
#define PAIRJ 312500           // EE/4 thread-groups; each thread does 4 edges (2 pairs)
#define HH 64
#define BB 500
#define BN_EPS 1e-5f

#define NB2 2048
#define XLO (-8.0f)
#define INVH2 128.0f           // NB2/16
#define H2 0.0078125f          // 16/NB2
#define TROWS 2112             // 33*64 >= NB2+1

// ---------------- device scratch ----------------
__device__ float   g_T[TROWS * HH];      // fp32 table at bin edges (pre-affine, for stats)
__device__ uint4   g_Tp[NB2 * 16];       // paired fp16 table: rows (b, b+1) per lane, 512KB
__device__ __half2 g_emh[100 * 32];      // fp16 edge_emb
__device__ __half2 g_hh[NN * 32];        // fp16 node features (gather side), 6.4MB
__device__ int2    g_rec[EE];            // src|dst<<16, ty|bin<<7|wq<<18
__device__ float   g_hist[3 * NB2];      // n, sum(w), sum(w^2)  (quantized w)
__device__ float   g_agg[NN * HH];       // fp32 accumulator
__device__ float   g_hg[BB * HH];
__device__ float   g_y1[NN * 64];
__device__ float   g_y2[NN * 32];
__device__ float   g_red[22592];
__device__ float   g_coef[1024];

#define OFF_X   0
#define OFF_D2  64
#define OFF_C1  4160
#define OFF_C2  8256
#define OFF_C3  12352
#define OFF_O1  16448
#define OFF_O2  20544

__device__ __forceinline__ float sp(float x) {
    float t, l;
    asm("ex2.approx.ftz.f32 %0, %1;" : "=f"(t) : "f"(x * 1.44269504f));
    asm("lg2.approx.f32 %0, %1;" : "=f"(l) : "f"(1.0f + t));
    float r = l * 0.69314718f;
    return x > 20.0f ? x : r;
}

// ---------------- setup kernels ----------------

__global__ void kzero() {
    int i = blockIdx.x * 256 + threadIdx.x;
    if (i < 22592) g_red[i] = 0.0f;
    if (i < BB * HH) g_hg[i] = 0.0f;
    if (i < 3 * NB2) g_hist[i] = 0.0f;
}

// stride-loop over edges: pack records, smem histogram (n, w, w^2), x stats
__global__ void kprep(const int* __restrict__ ei, const int* __restrict__ et,
                      const float* __restrict__ x) {
    __shared__ float hn[NB2], hw[NB2], hw2[NB2];
    __shared__ float sxs[2];
    int t = threadIdx.x;
    for (int i = t; i < NB2; i += 256) { hn[i] = 0; hw[i] = 0; hw2[i] = 0; }
    if (t < 2) sxs[t] = 0.f;
    __syncthreads();

    float sx = 0.f, sxx = 0.f;
    for (int e = blockIdx.x * 256 + t; e < EE; e += gridDim.x * 256) {
        float xv = x[e];
        sx += xv; sxx += xv * xv;
        float u = (xv - XLO) * INVH2;
        u = fminf(fmaxf(u, 0.0f), (float)NB2);
        int b = (int)u; if (b > NB2 - 1) b = NB2 - 1;
        int wq = (int)((u - (float)b) * 16383.0f + 0.5f);
        float w = (float)wq * (1.0f / 16383.0f);
        atomicAdd(&hn[b], 1.0f);
        atomicAdd(&hw[b], w);
        atomicAdd(&hw2[b], w * w);
        g_rec[e] = make_int2(ei[e] | (ei[EE + e] << 16),
                             et[e] | (b << 7) | (wq << 18));
    }
    atomicAdd(&sxs[0], sx);
    atomicAdd(&sxs[1], sxx);
    __syncthreads();
    for (int i = t * 4; i < NB2; i += 1024) {
        float4 a = *(const float4*)&hn[i];
        float4 b = *(const float4*)&hw[i];
        float4 c = *(const float4*)&hw2[i];
        asm volatile("red.global.add.v4.f32 [%0], {%1, %2, %3, %4};"
                     :: "l"(&g_hist[i]), "f"(a.x), "f"(a.y), "f"(a.z), "f"(a.w) : "memory");
        asm volatile("red.global.add.v4.f32 [%0], {%1, %2, %3, %4};"
                     :: "l"(&g_hist[NB2 + i]), "f"(b.x), "f"(b.y), "f"(b.z), "f"(b.w) : "memory");
        asm volatile("red.global.add.v4.f32 [%0], {%1, %2, %3, %4};"
                     :: "l"(&g_hist[2 * NB2 + i]), "f"(c.x), "f"(c.y), "f"(c.z), "f"(c.w) : "memory");
    }
    if (t == 0) {
        int r = blockIdx.x & 31;
        atomicAdd(&g_red[OFF_X + 2 * r], sxs[0]);
        atomicAdd(&g_red[OFF_X + 2 * r + 1], sxs[1]);
    }
}

__global__ void kfin_d1(const float* __restrict__ w_d1, const float* __restrict__ g_d1,
                        const float* __restrict__ be_d1) {
    __shared__ float S[2];
    if (threadIdx.x == 0) {
        float s = 0.f, q = 0.f;
        for (int r = 0; r < 32; r++) { s += g_red[2 * r]; q += g_red[2 * r + 1]; }
        S[0] = s; S[1] = q;
    }
    __syncthreads();
    float mx = S[0] / (float)EE;
    float vx = S[1] / (float)EE - mx * mx;
    int h = threadIdx.x;
    float w = w_d1[h];
    float a = w * rsqrtf(vx * w * w + BN_EPS) * g_d1[h];
    g_coef[h] = a;
    g_coef[64 + h] = -mx * a + be_d1[h];
}

// table build at bin-edge nodes: tiled GEMM, block = 64 rows x 64 k
__global__ void ktable(const float* __restrict__ w_d2) {
    __shared__ float w2s[64 * 68];
    __shared__ float spv[64 * 64];
    int t = threadIdx.x;
    int j0 = blockIdx.x * 64;

    for (int i = t * 4; i < 4096; i += 1024) {
        float4 v = __ldg((const float4*)&w_d2[i]);
        int k = i >> 6, f = i & 63;
        *(float4*)&w2s[k * 68 + f] = v;
    }
    {
        int f = t & 63;
        float a = g_coef[f], c = g_coef[64 + f];
        for (int j = t >> 6; j < 64; j += 4) {
            float xj = XLO + (float)(j0 + j) * H2;
            spv[j * 64 + f] = sp(a * xj + c);
        }
    }
    __syncthreads();

    int k = t & 63;
    int jg = (t >> 6) * 16;
    float acc[16];
#pragma unroll
    for (int i = 0; i < 16; i++) acc[i] = 0.f;
    for (int f4 = 0; f4 < 64; f4 += 4) {
        float4 w4 = *(const float4*)&w2s[k * 68 + f4];
#pragma unroll
        for (int i = 0; i < 16; i++) {
            float4 d = *(const float4*)&spv[(jg + i) * 64 + f4];
            acc[i] += d.x * w4.x + d.y * w4.y + d.z * w4.z + d.w * w4.w;
        }
    }
#pragma unroll
    for (int i = 0; i < 16; i++)
        g_T[(j0 + jg + i) * 64 + k] = acc[i];
}

// BN2 stats from histogram moments; 256 blocks x 64 threads, 8 bins each
__global__ void kd2stat() {
    int k = threadIdx.x;
    int b0 = blockIdx.x * 8;
    float s = 0.f, q = 0.f;
    float tp = g_T[b0 * 64 + k];
    for (int j = 0; j < 8; j++) {
        int b = b0 + j;
        float tn = g_T[(b + 1) * 64 + k];
        float n  = g_hist[b];
        float c1 = g_hist[NB2 + b];
        float s2 = g_hist[2 * NB2 + b];
        float c0 = n - c1;
        float s1 = c1 - s2;
        float s0 = n - 2.0f * c1 + s2;
        s += c0 * tp + c1 * tn;
        q += s0 * tp * tp + 2.0f * s1 * tp * tn + s2 * tn * tn;
        tp = tn;
    }
    int r = blockIdx.x & 31;
    atomicAdd(&g_red[OFF_D2 + r * 128 + k], s);
    atomicAdd(&g_red[OFF_D2 + r * 128 + 64 + k], q);
}

__global__ void kfinbn(int redoff, int F, float cnt, const float* __restrict__ g,
                       const float* __restrict__ be, int coefoff) {
    int k = threadIdx.x;
    if (k >= F) return;
    float s = 0.f, q = 0.f;
    for (int r = 0; r < 32; r++) {
        s += g_red[redoff + r * 2 * F + k];
        q += g_red[redoff + r * 2 * F + F + k];
    }
    float m = s / cnt;
    float v = q / cnt - m * m;
    float sc = g[k] * rsqrtf(v + BN_EPS);
    g_coef[coefoff + k] = sc;
    g_coef[coefoff + 64 + k] = be[k] - m * sc;
}

// fold BN2 affine into paired fp16 table: g_Tp[b*16+l] = {T(b)[4l..4l+3], T(b+1)[4l..4l+3]}
__global__ void ktaffine() {
    int i = blockIdx.x * 256 + threadIdx.x;
    if (i >= NB2 * 16) return;
    int b = i >> 4;
    int f = (i & 15) * 4;
    float sc0 = g_coef[128 + f], sc1 = g_coef[128 + f + 1];
    float sc2 = g_coef[128 + f + 2], sc3 = g_coef[128 + f + 3];
    float sh0 = g_coef[192 + f], sh1 = g_coef[192 + f + 1];
    float sh2 = g_coef[192 + f + 2], sh3 = g_coef[192 + f + 3];
    const float* ra = &g_T[b * 64 + f];
    const float* rb = &g_T[(b + 1) * 64 + f];
    uint4 out;
    *(__half2*)&out.x = __floats2half2_rn(ra[0] * sc0 + sh0, ra[1] * sc1 + sh1);
    *(__half2*)&out.y = __floats2half2_rn(ra[2] * sc2 + sh2, ra[3] * sc3 + sh3);
    *(__half2*)&out.z = __floats2half2_rn(rb[0] * sc0 + sh0, rb[1] * sc1 + sh1);
    *(__half2*)&out.w = __floats2half2_rn(rb[2] * sc2 + sh2, rb[3] * sc3 + sh3);
    g_Tp[i] = out;
}

__global__ void kemh(const float* __restrict__ edge_emb) {
    int i = blockIdx.x * 256 + threadIdx.x;
    if (i >= 100 * 32) return;
    g_emh[i] = __floats2half2_rn(edge_emb[2 * i], edge_emb[2 * i + 1]);
}

__global__ void kinith(const int* __restrict__ node_type, const float* __restrict__ node_emb) {
    int i = blockIdx.x * 256 + threadIdx.x;   // N*32: two features per thread
    int n = i >> 5, k2 = (i & 31) * 2;
    float v0 = node_emb[node_type[n] * 64 + k2];
    float v1 = node_emb[node_type[n] * 64 + k2 + 1];
    g_hh[i] = __floats2half2_rn(v0, v1);
    g_agg[n * 64 + k2] = v0;
    g_agg[n * 64 + k2 + 1] = v1;
}

// ---------------- gconv: 16 thr/edge-slice, 4 edges/thread, fp16 h gather ----------------
__global__ void kedge() {
    int idx = blockIdx.x * 256 + threadIdx.x;
    int j = idx >> 4;
    if (j >= PAIRJ) return;
    int l = idx & 15;
    int l2 = l * 2;
    int f0 = l * 4;

    int4 ra = __ldg(&((const int4*)g_rec)[j]);
    int4 rb = __ldg(&((const int4*)g_rec)[j + PAIRJ]);

    int sd0 = ra.x, mt0 = ra.y;
    int sd1 = ra.z, mt1 = ra.w;
    int sd2 = rb.x, mt2 = rb.y;
    int sd3 = rb.z, mt3 = rb.w;

    int b0 = (mt0 >> 7) & 2047, b1 = (mt1 >> 7) & 2047;
    int b2 = (mt2 >> 7) & 2047, b3 = (mt3 >> 7) & 2047;
    float w0 = (float)((unsigned)mt0 >> 18) * (1.0f / 16383.0f);
    float w1 = (float)((unsigned)mt1 >> 18) * (1.0f / 16383.0f);
    float w2 = (float)((unsigned)mt2 >> 18) * (1.0f / 16383.0f);
    float w3 = (float)((unsigned)mt3 >> 18) * (1.0f / 16383.0f);

    uint4 t0 = __ldg(&g_Tp[b0 * 16 + l]);
    uint4 t1 = __ldg(&g_Tp[b1 * 16 + l]);
    uint4 t2 = __ldg(&g_Tp[b2 * 16 + l]);
    uint4 t3 = __ldg(&g_Tp[b3 * 16 + l]);

    uint2 e0 = __ldg((const uint2*)&g_emh[(mt0 & 127) * 32 + l2]);
    uint2 e1 = __ldg((const uint2*)&g_emh[(mt1 & 127) * 32 + l2]);
    uint2 e2 = __ldg((const uint2*)&g_emh[(mt2 & 127) * 32 + l2]);
    uint2 e3 = __ldg((const uint2*)&g_emh[(mt3 & 127) * 32 + l2]);

    uint2 h0 = __ldg((const uint2*)&g_hh[((unsigned)sd0 & 0xffffu) * 32 + l2]);
    uint2 h1 = __ldg((const uint2*)&g_hh[((unsigned)sd1 & 0xffffu) * 32 + l2]);
    uint2 h2 = __ldg((const uint2*)&g_hh[((unsigned)sd2 & 0xffffu) * 32 + l2]);
    uint2 h3 = __ldg((const uint2*)&g_hh[((unsigned)sd3 & 0xffffu) * 32 + l2]);

#define EDGE_MSG(tp, ee, hh, ww, sd)                                            \
    {                                                                           \
        float2 a0 = __half22float2(*(const __half2*)&tp.x);                     \
        float2 a1 = __half22float2(*(const __half2*)&tp.y);                     \
        float2 c0 = __half22float2(*(const __half2*)&tp.z);                     \
        float2 c1 = __half22float2(*(const __half2*)&tp.w);                     \
        float2 u0 = __half22float2(*(const __half2*)&ee.x);                     \
        float2 u1 = __half22float2(*(const __half2*)&ee.y);                     \
        float2 hA = __half22float2(*(const __half2*)&hh.x);                     \
        float2 hB = __half22float2(*(const __half2*)&hh.y);                     \
        float m0 = sp(hA.x + fmaf(ww, c0.x - a0.x, a0.x) * u0.x);               \
        float m1 = sp(hA.y + fmaf(ww, c0.y - a0.y, a0.y) * u0.y);               \
        float m2 = sp(hB.x + fmaf(ww, c1.x - a1.x, a1.x) * u1.x);               \
        float m3 = sp(hB.y + fmaf(ww, c1.y - a1.y, a1.y) * u1.y);               \
        float* o = &g_agg[((unsigned)sd >> 16) * 64 + f0];                      \
        asm volatile("red.global.add.v4.f32 [%0], {%1, %2, %3, %4};"            \
                     :: "l"(o), "f"(m0), "f"(m1), "f"(m2), "f"(m3) : "memory"); \
    }

    EDGE_MSG(t0, e0, h0, w0, sd0)
    EDGE_MSG(t1, e1, h1, w1, sd1)
    EDGE_MSG(t2, e2, h2, w2, sd2)
    EDGE_MSG(t3, e3, h3, w3, sd3)
#undef EDGE_MSG
}

// node stats: 782 blocks x 256 thr; each block covers 64 nodes with 4 independent loads/thread
__global__ void knstat(int redoff) {
    int t = threadIdx.x;
    int f0 = (t & 15) * 4;
    int n0 = blockIdx.x * 64 + (t >> 4);
    float4 v0, v1, v2, v3;
    bool k0 = (n0 < NN), k1 = (n0 + 16 < NN), k2 = (n0 + 32 < NN), k3 = (n0 + 48 < NN);
    if (k0) v0 = *(const float4*)&g_agg[n0 * 64 + f0];
    if (k1) v1 = *(const float4*)&g_agg[(n0 + 16) * 64 + f0];
    if (k2) v2 = *(const float4*)&g_agg[(n0 + 32) * 64 + f0];
    if (k3) v3 = *(const float4*)&g_agg[(n0 + 48) * 64 + f0];
    float4 s = {0, 0, 0, 0}, q = {0, 0, 0, 0};
#define ACC(vv, kk)                                                     \
    if (kk) {                                                           \
        s.x += vv.x; s.y += vv.y; s.z += vv.z; s.w += vv.w;             \
        q.x += vv.x * vv.x; q.y += vv.y * vv.y;                         \
        q.z += vv.z * vv.z; q.w += vv.w * vv.w;                         \
    }
    ACC(v0, k0) ACC(v1, k1) ACC(v2, k2) ACC(v3, k3)
#undef ACC
    __shared__ float ssum[64], ssq[64];
    if (t < 64) { ssum[t] = 0.f; ssq[t] = 0.f; }
    __syncthreads();
    atomicAdd(&ssum[f0 + 0], s.x); atomicAdd(&ssum[f0 + 1], s.y);
    atomicAdd(&ssum[f0 + 2], s.z); atomicAdd(&ssum[f0 + 3], s.w);
    atomicAdd(&ssq[f0 + 0], q.x); atomicAdd(&ssq[f0 + 1], q.y);
    atomicAdd(&ssq[f0 + 2], q.z); atomicAdd(&ssq[f0 + 3], q.w);
    __syncthreads();
    if (t < 64) {
        int r = blockIdx.x & 31;
        atomicAdd(&g_red[redoff + r * 128 + t], ssum[t]);
        atomicAdd(&g_red[redoff + r * 128 + 64 + t], ssq[t]);
    }
}

__global__ void kapply(int coefoff, int doact, int dohg, const int* __restrict__ batch) {
    int i = blockIdx.x * 256 + threadIdx.x;
    int n = i >> 4;
    int f0 = (i & 15) * 4;
    float4 v  = *(const float4*)&g_agg[n * 64 + f0];
    float4 sc = *(const float4*)&g_coef[coefoff + f0];
    float4 sh = *(const float4*)&g_coef[coefoff + 64 + f0];
    v.x = v.x * sc.x + sh.x; v.y = v.y * sc.y + sh.y;
    v.z = v.z * sc.z + sh.z; v.w = v.w * sc.w + sh.w;
    if (doact) {
        v.x = sp(v.x); v.y = sp(v.y); v.z = sp(v.z); v.w = sp(v.w);
        uint2 hout;
        *(__half2*)&hout.x = __floats2half2_rn(v.x, v.y);
        *(__half2*)&hout.y = __floats2half2_rn(v.z, v.w);
        *(uint2*)&g_hh[n * 32 + (i & 15) * 2] = hout;   // gather copy for next kedge
    }
    *(float4*)&g_agg[n * 64 + f0] = v;   // fp32 h (self term / output stage)
    if (dohg) {
        int b = batch[n];
        float* o = &g_hg[b * 64 + f0];
        asm volatile("red.global.add.v4.f32 [%0], {%1, %2, %3, %4};"
                     :: "l"(o), "f"(v.x), "f"(v.y), "f"(v.z), "f"(v.w) : "memory");
    }
}

// out MLP stage 1: 16 nodes per block; reads fp32 h from g_agg
__global__ void kstage1(const int* __restrict__ batch, const float* __restrict__ w_o1,
                        const float* __restrict__ b_o1) {
    __shared__ float snf[4][128];
    __shared__ float ssum[64], ssq[64];
    int t = threadIdx.x, q = t >> 6, k = t & 63;
    float asum = 0.f, asq = 0.f;
    float bias = b_o1[k];
#pragma unroll 1
    for (int it = 0; it < 4; it++) {
        int n = blockIdx.x * 16 + it * 4 + q;
        __syncthreads();
        snf[q][k]      = g_agg[n * 64 + k];
        snf[q][64 + k] = g_hg[batch[n] * 64 + k];
        __syncthreads();
        float acc = bias;
#pragma unroll
        for (int j4 = 0; j4 < 32; j4++) {
            float4 w4 = __ldg((const float4*)&w_o1[k * 128 + j4 * 4]);
            float4 v = *(const float4*)&snf[q][j4 * 4];
            acc += v.x * w4.x + v.y * w4.y + v.z * w4.z + v.w * w4.w;
        }
        g_y1[n * 64 + k] = acc;
        asum += acc; asq += acc * acc;
    }
    if (t < 64) { ssum[t] = 0.f; ssq[t] = 0.f; }
    __syncthreads();
    atomicAdd(&ssum[k], asum);
    atomicAdd(&ssq[k], asq);
    __syncthreads();
    if (t < 64) {
        int r = blockIdx.x & 31;
        atomicAdd(&g_red[OFF_O1 + r * 128 + t], ssum[t]);
        atomicAdd(&g_red[OFF_O1 + r * 128 + 64 + t], ssq[t]);
    }
}

// stage 2: 16 nodes per block
__global__ void kstage2(const float* __restrict__ w_o2, const float* __restrict__ b_o2) {
    __shared__ float sv[4][64];
    __shared__ float ssum[32], ssq[32];
    int t = threadIdx.x, q = t >> 5, k = t & 31;
    float asum = 0.f, asq = 0.f;
    float bias = b_o2[k];
#pragma unroll 1
    for (int it = 0; it < 4; it++) {
        int n = blockIdx.x * 16 + it * 4 + q;
        __syncthreads();
        {
            float a = g_y1[n * 64 + k]      * g_coef[640 + k]      + g_coef[704 + k];
            float b = g_y1[n * 64 + 32 + k] * g_coef[640 + 32 + k] + g_coef[704 + 32 + k];
            sv[q][k] = sp(a);
            sv[q][32 + k] = sp(b);
        }
        __syncthreads();
        float acc = bias;
#pragma unroll
        for (int j4 = 0; j4 < 16; j4++) {
            float4 w4 = __ldg((const float4*)&w_o2[k * 64 + j4 * 4]);
            float4 v = *(const float4*)&sv[q][j4 * 4];
            acc += v.x * w4.x + v.y * w4.y + v.z * w4.z + v.w * w4.w;
        }
        g_y2[n * 32 + k] = acc;
        asum += acc; asq += acc * acc;
    }
    if (t < 32) { ssum[t] = 0.f; ssq[t] = 0.f; }
    __syncthreads();
    atomicAdd(&ssum[k], asum);
    atomicAdd(&ssq[k], asq);
    __syncthreads();
    if (t < 32) {
        int r = blockIdx.x & 31;
        atomicAdd(&g_red[OFF_O2 + r * 64 + t], ssum[t]);
        atomicAdd(&g_red[OFF_O2 + r * 64 + 32 + t], ssq[t]);
    }
}

// stage 3: 16 nodes per block (8 iterations of 2)
__global__ void kstage3(const float* __restrict__ w_o3, const float* __restrict__ b_o3,
                        float* __restrict__ out) {
    __shared__ float sv[2][32];
    int t = threadIdx.x;
    int q = t >> 7, c = t & 127;
    float bias = b_o3[c];
#pragma unroll 1
    for (int it = 0; it < 8; it++) {
        int n2 = blockIdx.x * 16 + it * 2;
        __syncthreads();
        if (t < 64) {
            int qq = t >> 5, k = t & 31;
            float a = g_y2[(n2 + qq) * 32 + k] * g_coef[768 + k] + g_coef[832 + k];
            sv[qq][k] = sp(a);
        }
        __syncthreads();
        int n = n2 + q;
        float acc = bias;
#pragma unroll
        for (int j4 = 0; j4 < 8; j4++) {
            float4 w4 = __ldg((const float4*)&w_o3[c * 32 + j4 * 4]);
            float4 v = *(const float4*)&sv[q][j4 * 4];
            acc += v.x * w4.x + v.y * w4.y + v.z * w4.z + v.w * w4.w;
        }
        if (c < 64) out[(long)n * 64 + c] = acc;
        else        out[(long)NN * 64 + (long)n * 64 + (c - 64)] = acc;
    }
}

// ---------------- launch ----------------
extern "C" void kernel_launch(void* const* d_in, const int* in_sizes, int n_in,
                              void* d_out, int out_size) {
    const float* x         = (const float*)d_in[0];
    const int*   node_type = (const int*)d_in[1];
    const int*   edge_type = (const int*)d_in[2];
    const int*   edge_index= (const int*)d_in[3];
    const int*   batch     = (const int*)d_in[4];
    const float* node_emb  = (const float*)d_in[5];
    const float* edge_emb  = (const float*)d_in[6];
    const float* w_d1      = (const float*)d_in[7];
    const float* g_d1      = (const float*)d_in[9];
    const float* be_d1     = (const float*)d_in[10];
    const float* w_d2      = (const float*)d_in[11];
    const float* g_d2      = (const float*)d_in[13];
    const float* be_d2     = (const float*)d_in[14];
    const float* g_c1      = (const float*)d_in[15];
    const float* be_c1     = (const float*)d_in[16];
    const float* g_c2      = (const float*)d_in[17];
    const float* be_c2     = (const float*)d_in[18];
    const float* g_c3      = (const float*)d_in[19];
    const float* be_c3     = (const float*)d_in[20];
    const float* w_o1      = (const float*)d_in[21];
    const float* b_o1      = (const float*)d_in[22];
    const float* g_o1      = (const float*)d_in[23];
    const float* be_o1     = (const float*)d_in[24];
    const float* w_o2      = (const float*)d_in[25];
    const float* b_o2      = (const float*)d_in[26];
    const float* g_o2      = (const float*)d_in[27];
    const float* be_o2     = (const float*)d_in[28];
    const float* w_o3      = (const float*)d_in[29];
    const float* b_o3      = (const float*)d_in[30];

    kzero<<<128, 256>>>();
    kprep<<<296, 256>>>(edge_index, edge_type, x);
    kfin_d1<<<1, 64>>>(w_d1, g_d1, be_d1);
    ktable<<<TROWS / 64, 256>>>(w_d2);
    kd2stat<<<NB2 / 8, 64>>>();
    kfinbn<<<1, 64>>>(OFF_D2, 64, (float)EE, g_d2, be_d2, 128);
    ktaffine<<<(NB2 * 16 + 255) / 256, 256>>>();
    kemh<<<13, 256>>>(edge_emb);
    kinith<<<(NN * 32 + 255) / 256, 256>>>(node_type, node_emb);

    const int   statoff[3] = {OFF_C1, OFF_C2, OFF_C3};
    const int   coefoff[3] = {256, 384, 512};
    const float* gs[3]  = {g_c1, g_c2, g_c3};
    const float* bes[3] = {be_c1, be_c2, be_c3};
    for (int l = 0; l < 3; l++) {
        kedge<<<(PAIRJ * 16 + 255) / 256, 256>>>();
        knstat<<<(NN + 63) / 64, 256>>>(statoff[l]);
        kfinbn<<<1, 64>>>(statoff[l], 64, (float)NN, gs[l], bes[l], coefoff[l]);
        kapply<<<3125, 256>>>(coefoff[l], (l < 2) ? 1 : 0, (l == 2) ? 1 : 0, batch);
    }

    kstage1<<<3125, 256>>>(batch, w_o1, b_o1);
    kfinbn<<<1, 64>>>(OFF_O1, 64, (float)NN, g_o1, be_o1, 640);
    kstage2<<<3125, 128>>>(w_o2, b_o2);
    kfinbn<<<1, 64>>>(OFF_O2, 32, (float)NN, g_o2, be_o2, 768);
    kstage3<<<3125, 256>>>(w_o3, b_o3, (float*)d_out);
}